// round 13
// baseline (speedup 1.0000x reference)
#include <cuda_runtime.h>
#include <cuda_bf16.h>
#include <cstdint>

#define BQ 8
#define TT 2048
#define CC 512
#define HH 16
#define HSZ 32
#define BT (BQ*TT)            // 16384
#define UEL ((size_t)BT*CC)   // 8388608 elements per [B,T,C] buffer
#define NCH 16                // chunks per sequence
#define CHL 128               // chunk length (TT/NCH)
#define NCID (BQ*HH*NCH)      // 2048 total chunks

// ---------------------------------------------------------------------------
// Scratch (bytes). One big device array; no allocations anywhere.
// ---------------------------------------------------------------------------
#define SZ_F32   (UEL*4)
#define SZ_BF16  (UEL*2)
#define SZ_MIX   ((size_t)BT*160*4)
#define SZ_W64B  ((size_t)BT*64*2)
#define SZ_WBF   ((size_t)CC*CC*2)
#define SZ_L     ((size_t)NCID*1024*4)
#define SZ_P     ((size_t)NCID*32*4)

#define O_MIX   ((size_t)0)
#define O_XWH   (O_MIX + SZ_MIX)
#define O_XWL   (O_XWH + SZ_BF16)
#define O_W64H  (O_XWL + SZ_BF16)
#define O_W64L  (O_W64H + SZ_W64B)
#define O_DB    (O_W64L + SZ_W64B)
#define O_RB    (O_DB + SZ_F32)
#define O_KB    (O_RB + SZ_F32)
#define O_VB    (O_KB + SZ_F32)
#define O_GB    (O_VB + SZ_F32)
#define O_YB    (O_GB + SZ_F32)
#define O_AB    (O_YB + SZ_F32)
#define O_LB    (O_AB + SZ_F32)
#define O_PB    (O_LB + SZ_L)
#define O_S0    (O_PB + SZ_P)
#define O_KH    (O_S0 + SZ_L)
#define O_KL    (O_KH + SZ_BF16)
#define O_VH    (O_KL + SZ_BF16)
#define O_VL    (O_VH + SZ_BF16)
#define O_RH    (O_VL + SZ_BF16)
#define O_RL    (O_RH + SZ_BF16)
#define O_GH    (O_RL + SZ_BF16)
#define O_GL    (O_GH + SZ_BF16)
#define O_ZH    (O_GL + SZ_BF16)
#define O_ZL    (O_ZH + SZ_BF16)
#define O_XXH   (O_ZL + SZ_BF16)
#define O_XXL   (O_XXH + SZ_BF16)
#define O_WRH   (O_XXL + SZ_BF16)
#define O_WRL   (O_WRH + SZ_WBF)
#define O_WKH   (O_WRL + SZ_WBF)
#define O_WKL   (O_WKH + SZ_WBF)
#define O_WVH   (O_WKL + SZ_WBF)
#define O_WVL   (O_WVH + SZ_WBF)
#define O_WGH   (O_WVL + SZ_WBF)
#define O_WGL   (O_WGH + SZ_WBF)
#define O_WOH   (O_WGL + SZ_WBF)
#define O_WOL   (O_WOH + SZ_WBF)
#define O_T1H   (O_WOL + SZ_WBF)                 // tdw1^T padded: 128x512 bf16
#define O_T1L   (O_T1H + (size_t)128*512*2)
#define O_T2H   (O_T1L + (size_t)128*512*2)      // tdw2^T: 512x64 bf16
#define O_T2L   (O_T2H + (size_t)512*64*2)
#define O_M1H   (O_T2L + (size_t)512*64*2)       // w1^T padded: 256x512 bf16
#define O_M1L   (O_M1H + (size_t)256*512*2)
#define O_MIXP  (O_M1L + (size_t)256*512*2)      // 5 planes of (BT,512) bf16
#define O_W2T   (O_MIXP + (size_t)5*UEL*2)       // W2^T: 5 x 512 x 32 bf16
#define SCRATCH_BYTES (O_W2T + (size_t)5*512*32*2)

__device__ __align__(256) unsigned char g_scratch[SCRATCH_BYTES];

// ---------------------------------------------------------------------------
// mma.sync / cp.async helpers (valid on plain compute_103 / sm_80+)
// ---------------------------------------------------------------------------
__device__ __forceinline__ uint32_t smem_u32(const void* p) {
    uint32_t a;
    asm("{ .reg .u64 t; cvta.to.shared.u64 t, %1; cvt.u32.u64 %0, t; }"
        : "=r"(a) : "l"(p));
    return a;
}

#define LDSM4(r, a) \
    asm volatile("ldmatrix.sync.aligned.m8n8.x4.shared.b16 {%0,%1,%2,%3}, [%4];" \
        : "=r"((r)[0]), "=r"((r)[1]), "=r"((r)[2]), "=r"((r)[3]) : "r"(a))

#define MMA16816(d, a, b0, b1) \
    asm volatile("mma.sync.aligned.m16n8k16.row.col.f32.bf16.bf16.f32 " \
        "{%0,%1,%2,%3}, {%4,%5,%6,%7}, {%8,%9}, {%0,%1,%2,%3};" \
        : "+f"((d)[0]), "+f"((d)[1]), "+f"((d)[2]), "+f"((d)[3]) \
        : "r"((a)[0]), "r"((a)[1]), "r"((a)[2]), "r"((a)[3]), "r"(b0), "r"(b1))

#define CP_ASYNC16(dst, src) \
    asm volatile("cp.async.cg.shared.global [%0], [%1], 16;" :: "r"(dst), "l"(src))
#define CP_COMMIT() asm volatile("cp.async.commit_group;" ::: "memory")
#define CP_WAIT(n)  asm volatile("cp.async.wait_group %0;" :: "n"(n) : "memory")

#define TROWB 80
#define TTILE (128*TROWB)     // 10240
#define TSTAGE (4*TTILE)      // 40960
#define TG_SMEM (2*TSTAGE)    // 81920
#define ROWSKIP (64*1024)     // 64 rows * 512 cols * 2B (K=512 path)
#define DSTSKIP (64*TROWB)

// ---------------------------------------------------------------------------
// split / pack helpers
// ---------------------------------------------------------------------------
__device__ __forceinline__ void wsplit(float v, __nv_bfloat16* hi, __nv_bfloat16* lo, size_t i) {
    __nv_bfloat16 h = __float2bfloat16(v);
    hi[i] = h;
    lo[i] = __float2bfloat16(v - __bfloat162float(h));
}
__device__ __forceinline__ uint32_t pack_bf2(float a, float b) {
    __nv_bfloat162 p;
    p.x = __float2bfloat16(a);
    p.y = __float2bfloat16(b);
    return *reinterpret_cast<uint32_t*>(&p);
}

// Software-pipelined mainloop body (shared by tgemm / tgemm2). B fragments
// double-buffered so LDSM for nt+1 overlaps the 12 MMAs of nt.
#define TG_COMPUTE_CHUNK(ra0, rb0)                                            \
    _Pragma("unroll")                                                         \
    for (int ks = 0; ks < 2; ++ks) {                                          \
        uint32_t ah[2][4], al[2][4];                                          \
        _Pragma("unroll")                                                     \
        for (int mt = 0; mt < 2; ++mt) {                                      \
            uint32_t ra = (ra0) + mt * (16 * TROWB) + ks * 32;                \
            LDSM4(ah[mt], ra);                                                \
            LDSM4(al[mt], ra + TTILE);                                        \
        }                                                                     \
        uint32_t bh4[2][4], bl4[2][4];                                        \
        LDSM4(bh4[0], (rb0) + ks * 32);                                       \
        LDSM4(bl4[0], (rb0) + ks * 32 + TTILE);                               \
        _Pragma("unroll")                                                     \
        for (int nt = 0; nt < 4; ++nt) {                                      \
            int cur = nt & 1, nxt = cur ^ 1;                                  \
            if (nt < 3) {                                                     \
                uint32_t rb = (rb0) + (nt + 1) * (16 * TROWB) + ks * 32;      \
                LDSM4(bh4[nxt], rb);                                          \
                LDSM4(bl4[nxt], rb + TTILE);                                  \
            }                                                                 \
            _Pragma("unroll")                                                 \
            for (int mt = 0; mt < 2; ++mt) {                                  \
                MMA16816(acc[mt][nt*2+0], ah[mt], bh4[cur][0], bh4[cur][2]);  \
                MMA16816(acc[mt][nt*2+1], ah[mt], bh4[cur][1], bh4[cur][3]);  \
                MMA16816(acc[mt][nt*2+0], ah[mt], bl4[cur][0], bl4[cur][2]);  \
                MMA16816(acc[mt][nt*2+1], ah[mt], bl4[cur][1], bl4[cur][3]);  \
                MMA16816(acc[mt][nt*2+0], al[mt], bh4[cur][0], bh4[cur][2]);  \
                MMA16816(acc[mt][nt*2+1], al[mt], bh4[cur][1], bh4[cur][3]);  \
            }                                                                 \
        }                                                                     \
    }

// ---------------------------------------------------------------------------
// Pipelined tensor-core GEMM (hot path, K=512, N=512).
// ---------------------------------------------------------------------------
struct TGBatch {
    const __nv_bfloat16 *ah[4], *al[4], *bh[4], *bl[4];
    float* c[4];
};

template<bool BATCH, int EPI>
__global__ void __launch_bounds__(256, 2)
tgemm_kernel(TGBatch bt_,
             const __nv_bfloat16* __restrict__ Ah_, const __nv_bfloat16* __restrict__ Al_,
             const __nv_bfloat16* __restrict__ Bh_, const __nv_bfloat16* __restrict__ Bl_,
             float* __restrict__ C_)
{
    extern __shared__ unsigned char sm[];
    uint32_t smb = smem_u32(sm);
    int tid = threadIdx.x;
    int wid = tid >> 5, lane = tid & 31;
    int bm = blockIdx.y * 128, bn = blockIdx.x * 128;
    int wm = (wid & 3) * 32, wn = (wid >> 2) * 64;

    int z = BATCH ? blockIdx.z : 0;
    const __nv_bfloat16* Ah = BATCH ? bt_.ah[z] : Ah_;
    const __nv_bfloat16* Al = BATCH ? bt_.al[z] : Al_;
    const __nv_bfloat16* Bh = BATCH ? bt_.bh[z] : Bh_;
    const __nv_bfloat16* Bl = BATCH ? bt_.bl[z] : Bl_;
    float* C = BATCH ? bt_.c[z] : C_;
    bool do_silu = BATCH ? (z == 3) : (EPI == 2);

    int rowq = tid >> 2;
    int gcol = (tid & 3) * 8;
    const char* pAh = (const char*)(Ah + (size_t)(bm + rowq) * 512 + gcol);
    const char* pAl = (const char*)(Al + (size_t)(bm + rowq) * 512 + gcol);
    const char* pBh = (const char*)(Bh + (size_t)(bn + rowq) * 512 + gcol);
    const char* pBl = (const char*)(Bl + (size_t)(bn + rowq) * 512 + gcol);
    uint32_t dA = smb + rowq * TROWB + (tid & 3) * 16;
    uint32_t dB = dA + 2 * TTILE;

    float acc[2][8][4];
    #pragma unroll
    for (int i = 0; i < 2; ++i)
        #pragma unroll
        for (int j = 0; j < 8; ++j)
            #pragma unroll
            for (int q = 0; q < 4; ++q) acc[i][j][q] = 0.f;

    int mat = lane >> 3, r8 = lane & 7;
    int lrow = (mat & 1) * 8 + r8;
    int lkb  = (mat >> 1) * 16;
    uint32_t raBase = smb + (wm + lrow) * TROWB + lkb;
    uint32_t rbBase = smb + 2 * TTILE + (wn + lrow) * TROWB + lkb;

    {
        CP_ASYNC16(dA,                    pAh);
        CP_ASYNC16(dA + DSTSKIP,          pAh + ROWSKIP);
        CP_ASYNC16(dA + TTILE,            pAl);
        CP_ASYNC16(dA + TTILE + DSTSKIP,  pAl + ROWSKIP);
        CP_ASYNC16(dB,                    pBh);
        CP_ASYNC16(dB + DSTSKIP,          pBh + ROWSKIP);
        CP_ASYNC16(dB + TTILE,            pBl);
        CP_ASYNC16(dB + TTILE + DSTSKIP,  pBl + ROWSKIP);
        pAh += 64; pAl += 64; pBh += 64; pBl += 64;
        CP_COMMIT();
    }

    for (int ch = 0; ch < 16; ++ch) {
        if (ch + 1 < 16) {
            uint32_t so = ((ch + 1) & 1) * TSTAGE;
            CP_ASYNC16(dA + so,                    pAh);
            CP_ASYNC16(dA + so + DSTSKIP,          pAh + ROWSKIP);
            CP_ASYNC16(dA + so + TTILE,            pAl);
            CP_ASYNC16(dA + so + TTILE + DSTSKIP,  pAl + ROWSKIP);
            CP_ASYNC16(dB + so,                    pBh);
            CP_ASYNC16(dB + so + DSTSKIP,          pBh + ROWSKIP);
            CP_ASYNC16(dB + so + TTILE,            pBl);
            CP_ASYNC16(dB + so + TTILE + DSTSKIP,  pBl + ROWSKIP);
            pAh += 64; pAl += 64; pBh += 64; pBl += 64;
            CP_COMMIT();
            CP_WAIT(1);
        } else {
            CP_WAIT(0);
        }
        __syncthreads();

        uint32_t so = (ch & 1) * TSTAGE;
        uint32_t ra0 = raBase + so;
        uint32_t rb0 = rbBase + so;
        TG_COMPUTE_CHUNK(ra0, rb0)
        __syncthreads();
    }

    int r0 = lane >> 2, c0 = (lane & 3) * 2;
    #pragma unroll
    for (int mt = 0; mt < 2; ++mt) {
        #pragma unroll
        for (int nt = 0; nt < 4; ++nt) {
            #pragma unroll
            for (int s = 0; s < 2; ++s) {
                float* a4 = acc[mt][nt*2+s];
                int col = bn + wn + nt * 16 + s * 8 + c0;
                int row = bm + wm + mt * 16 + r0;
                float v0 = a4[0], v1 = a4[1], v2 = a4[2], v3 = a4[3];
                if (do_silu) {
                    v0 = v0 / (1.f + __expf(-v0));
                    v1 = v1 / (1.f + __expf(-v1));
                    v2 = v2 / (1.f + __expf(-v2));
                    v3 = v3 / (1.f + __expf(-v3));
                }
                *reinterpret_cast<float2*>(C + (size_t)row * 512 + col)       = make_float2(v0, v1);
                *reinterpret_cast<float2*>(C + (size_t)(row + 8) * 512 + col) = make_float2(v2, v3);
            }
        }
    }
}

// ---------------------------------------------------------------------------
// Parameterized tensor GEMM (decay MLP + mix GEMM).
// NK = K/32 chunks. EPI: 1 tanh, 3 exp(-exp(bias+v)).
// OM: 0 fp32 out, 1 split bf16 hi/lo out, 2 single bf16 out.
// ---------------------------------------------------------------------------
template<int NK, int EPI, int OM>
__global__ void __launch_bounds__(256, 2)
tgemm2_kernel(const __nv_bfloat16* __restrict__ Ah, const __nv_bfloat16* __restrict__ Al,
              const __nv_bfloat16* __restrict__ Bh, const __nv_bfloat16* __restrict__ Bl,
              float* __restrict__ Cf,
              __nv_bfloat16* __restrict__ Chi, __nv_bfloat16* __restrict__ Clo,
              const float* __restrict__ bias, int N)
{
    constexpr int K = NK * 32;
    constexpr int RSKIP = 64 * K * 2;
    extern __shared__ unsigned char sm[];
    uint32_t smb = smem_u32(sm);
    int tid = threadIdx.x;
    int wid = tid >> 5, lane = tid & 31;
    int bm = blockIdx.y * 128, bn = blockIdx.x * 128;
    int wm = (wid & 3) * 32, wn = (wid >> 2) * 64;

    int rowq = tid >> 2;
    int gcol = (tid & 3) * 8;
    const char* pAh = (const char*)(Ah + (size_t)(bm + rowq) * K + gcol);
    const char* pAl = (const char*)(Al + (size_t)(bm + rowq) * K + gcol);
    const char* pBh = (const char*)(Bh + (size_t)(bn + rowq) * K + gcol);
    const char* pBl = (const char*)(Bl + (size_t)(bn + rowq) * K + gcol);
    uint32_t dA = smb + rowq * TROWB + (tid & 3) * 16;
    uint32_t dB = dA + 2 * TTILE;

    float acc[2][8][4];
    #pragma unroll
    for (int i = 0; i < 2; ++i)
        #pragma unroll
        for (int j = 0; j < 8; ++j)
            #pragma unroll
            for (int q = 0; q < 4; ++q) acc[i][j][q] = 0.f;

    int mat = lane >> 3, r8 = lane & 7;
    int lrow = (mat & 1) * 8 + r8;
    int lkb  = (mat >> 1) * 16;
    uint32_t raBase = smb + (wm + lrow) * TROWB + lkb;
    uint32_t rbBase = smb + 2 * TTILE + (wn + lrow) * TROWB + lkb;

    {
        CP_ASYNC16(dA,                   pAh);
        CP_ASYNC16(dA + DSTSKIP,         pAh + RSKIP);
        CP_ASYNC16(dA + TTILE,           pAl);
        CP_ASYNC16(dA + TTILE + DSTSKIP, pAl + RSKIP);
        CP_ASYNC16(dB,                   pBh);
        CP_ASYNC16(dB + DSTSKIP,         pBh + RSKIP);
        CP_ASYNC16(dB + TTILE,           pBl);
        CP_ASYNC16(dB + TTILE + DSTSKIP, pBl + RSKIP);
        pAh += 64; pAl += 64; pBh += 64; pBl += 64;
        CP_COMMIT();
    }

    for (int ch = 0; ch < NK; ++ch) {
        if (ch + 1 < NK) {
            uint32_t so = ((ch + 1) & 1) * TSTAGE;
            CP_ASYNC16(dA + so,                   pAh);
            CP_ASYNC16(dA + so + DSTSKIP,         pAh + RSKIP);
            CP_ASYNC16(dA + so + TTILE,           pAl);
            CP_ASYNC16(dA + so + TTILE + DSTSKIP, pAl + RSKIP);
            CP_ASYNC16(dB + so,                   pBh);
            CP_ASYNC16(dB + so + DSTSKIP,         pBh + RSKIP);
            CP_ASYNC16(dB + so + TTILE,           pBl);
            CP_ASYNC16(dB + so + TTILE + DSTSKIP, pBl + RSKIP);
            pAh += 64; pAl += 64; pBh += 64; pBl += 64;
            CP_COMMIT();
            CP_WAIT(1);
        } else {
            CP_WAIT(0);
        }
        __syncthreads();

        uint32_t so = (ch & 1) * TSTAGE;
        uint32_t ra0 = raBase + so;
        uint32_t rb0 = rbBase + so;
        TG_COMPUTE_CHUNK(ra0, rb0)
        __syncthreads();
    }

    int r0 = lane >> 2, c0 = (lane & 3) * 2;
    #pragma unroll
    for (int mt = 0; mt < 2; ++mt) {
        #pragma unroll
        for (int nt = 0; nt < 4; ++nt) {
            #pragma unroll
            for (int s = 0; s < 2; ++s) {
                float* a4 = acc[mt][nt*2+s];
                int col = bn + wn + nt * 16 + s * 8 + c0;
                if (col >= N) continue;
                int row = bm + wm + mt * 16 + r0;
                #pragma unroll
                for (int half = 0; half < 2; ++half) {
                    float v0 = a4[half * 2 + 0], v1 = a4[half * 2 + 1];
                    size_t ro = (size_t)(row + half * 8) * N + col;
                    if (EPI == 1) { v0 = tanhf(v0); v1 = tanhf(v1); }
                    else if (EPI == 3) {
                        v0 = __expf(-__expf(bias[col] + v0));
                        v1 = __expf(-__expf(bias[col + 1] + v1));
                    }
                    if (OM == 1) {
                        wsplit(v0, Chi, Clo, ro);
                        wsplit(v1, Chi, Clo, ro + 1);
                    } else if (OM == 2) {
                        *reinterpret_cast<uint32_t*>(Chi + ro) = pack_bf2(v0, v1);
                    } else {
                        *reinterpret_cast<float2*>(Cf + ro) = make_float2(v0, v1);
                    }
                }
            }
        }
    }
}

// ---------------------------------------------------------------------------
// Mix back-projection GEMM: mixproj_f = mix[:, f*32:(f+1)*32] @ W2T[f]
// ---------------------------------------------------------------------------
__global__ void __launch_bounds__(256)
tgemm3_kernel(const __nv_bfloat16* __restrict__ mixbh,
              const __nv_bfloat16* __restrict__ w2t,
              __nv_bfloat16* __restrict__ mixp)
{
    __shared__ unsigned char sm3[2 * TTILE];
    uint32_t smb = smem_u32(sm3);
    int tid = threadIdx.x;
    int wid = tid >> 5, lane = tid & 31;
    int bn = blockIdx.x * 128, bm = blockIdx.y * 128, f = blockIdx.z;
    int wm = (wid & 3) * 32, wn = (wid >> 2) * 64;

    #pragma unroll
    for (int q = 0; q < 2; ++q) {
        int e = tid * 2 + q;           // 0..511
        int row = e >> 2, g = e & 3;
        CP_ASYNC16(smb + row * TROWB + g * 16,
                   mixbh + (size_t)(bm + row) * 160 + f * 32 + g * 8);
        CP_ASYNC16(smb + TTILE + row * TROWB + g * 16,
                   w2t + (size_t)f * 512 * 32 + (size_t)(bn + row) * 32 + g * 8);
    }
    CP_COMMIT();
    CP_WAIT(0);
    __syncthreads();

    float acc[2][8][4];
    #pragma unroll
    for (int i = 0; i < 2; ++i)
        #pragma unroll
        for (int j = 0; j < 8; ++j)
            #pragma unroll
            for (int q = 0; q < 4; ++q) acc[i][j][q] = 0.f;

    int mat = lane >> 3, r8 = lane & 7;
    int lrow = (mat & 1) * 8 + r8;
    int lkb  = (mat >> 1) * 16;
    uint32_t ra0 = smb + (wm + lrow) * TROWB + lkb;
    uint32_t rb0 = smb + TTILE + (wn + lrow) * TROWB + lkb;

    #pragma unroll
    for (int ks = 0; ks < 2; ++ks) {
        uint32_t ah[2][4];
        #pragma unroll
        for (int mt = 0; mt < 2; ++mt)
            LDSM4(ah[mt], ra0 + mt * (16 * TROWB) + ks * 32);
        #pragma unroll
        for (int nt = 0; nt < 4; ++nt) {
            uint32_t bh4[4];
            LDSM4(bh4, rb0 + nt * (16 * TROWB) + ks * 32);
            #pragma unroll
            for (int mt = 0; mt < 2; ++mt) {
                MMA16816(acc[mt][nt*2+0], ah[mt], bh4[0], bh4[2]);
                MMA16816(acc[mt][nt*2+1], ah[mt], bh4[1], bh4[3]);
            }
        }
    }

    __nv_bfloat16* Cb = mixp + (size_t)f * UEL;
    int r0 = lane >> 2, c0 = (lane & 3) * 2;
    #pragma unroll
    for (int mt = 0; mt < 2; ++mt) {
        #pragma unroll
        for (int nt = 0; nt < 4; ++nt) {
            #pragma unroll
            for (int s = 0; s < 2; ++s) {
                float* a4 = acc[mt][nt*2+s];
                int col = bn + wn + nt * 16 + s * 8 + c0;
                int row = bm + wm + mt * 16 + r0;
                *reinterpret_cast<uint32_t*>(Cb + (size_t)row * 512 + col)       = pack_bf2(a4[0], a4[1]);
                *reinterpret_cast<uint32_t*>(Cb + (size_t)(row + 8) * 512 + col) = pack_bf2(a4[2], a4[3]);
            }
        }
    }
}

// ---------------------------------------------------------------------------
// Elementwise 5-way token mix apply: x_f = x + (xshift-x)*(maa_f + mixproj_f)
// ---------------------------------------------------------------------------
__global__ void __launch_bounds__(256) mixapply_kernel(
    const float* __restrict__ x, const __nv_bfloat16* __restrict__ mixp,
    const float* __restrict__ maaw, const float* __restrict__ maak,
    const float* __restrict__ maav, const float* __restrict__ maar,
    const float* __restrict__ maag,
    __nv_bfloat16* __restrict__ xwh, __nv_bfloat16* __restrict__ xwl,
    __nv_bfloat16* __restrict__ kh, __nv_bfloat16* __restrict__ kl,
    __nv_bfloat16* __restrict__ vh, __nv_bfloat16* __restrict__ vl,
    __nv_bfloat16* __restrict__ rh, __nv_bfloat16* __restrict__ rl,
    __nv_bfloat16* __restrict__ gh, __nv_bfloat16* __restrict__ gl)
{
    size_t i = ((size_t)blockIdx.x * 256 + threadIdx.x) * 4;
    int c = (int)(i & 511);
    int t = (int)((i >> 9) & (TT - 1));
    float4 xv = *reinterpret_cast<const float4*>(x + i);
    float4 xp = make_float4(0.f, 0.f, 0.f, 0.f);
    if (t) xp = *reinterpret_cast<const float4*>(x + i - 512);
    float xc[4] = {xv.x, xv.y, xv.z, xv.w};
    float xx[4] = {xp.x - xv.x, xp.y - xv.y, xp.z - xv.z, xp.w - xv.w};

    #pragma unroll
    for (int f = 0; f < 5; ++f) {
        const float* maa = (f == 0) ? maaw : (f == 1) ? maak : (f == 2) ? maav
                         : (f == 3) ? maar : maag;
        float4 m4 = *reinterpret_cast<const float4*>(maa + c);
        uint2 mp = *reinterpret_cast<const uint2*>(mixp + (size_t)f * UEL + i);
        __nv_bfloat162 m01 = *reinterpret_cast<__nv_bfloat162*>(&mp.x);
        __nv_bfloat162 m23 = *reinterpret_cast<__nv_bfloat162*>(&mp.y);
        float mv[4] = {__bfloat162float(m01.x), __bfloat162float(m01.y),
                       __bfloat162float(m23.x), __bfloat162float(m23.y)};
        float ma[4] = {m4.x, m4.y, m4.z, m4.w};
        float v[4], h[4];
        #pragma unroll
        for (int e = 0; e < 4; ++e) {
            v[e] = fmaf(xx[e], ma[e] + mv[e], xc[e]);
            h[e] = __bfloat162float(__float2bfloat16(v[e]));
        }
        uint2 hi2, lo2;
        hi2.x = pack_bf2(v[0], v[1]);
        hi2.y = pack_bf2(v[2], v[3]);
        lo2.x = pack_bf2(v[0] - h[0], v[1] - h[1]);
        lo2.y = pack_bf2(v[2] - h[2], v[3] - h[3]);
        __nv_bfloat16* dh = (f == 0) ? xwh : (f == 1) ? kh : (f == 2) ? vh
                          : (f == 3) ? rh : gh;
        __nv_bfloat16* dl = (f == 0) ? xwl : (f == 1) ? kl : (f == 2) ? vl
                          : (f == 3) ? rl : gl;
        *reinterpret_cast<uint2*>(dh + i) = hi2;
        *reinterpret_cast<uint2*>(dl + i) = lo2;
    }
}

// ---------------------------------------------------------------------------
// prep: xxx = x + (xshift - x) * maa_x  -> bf16 hi/lo
// ---------------------------------------------------------------------------
__global__ void __launch_bounds__(256) prep_split_kernel(
    const float* __restrict__ x, const float* __restrict__ tmx,
    __nv_bfloat16* __restrict__ xxh, __nv_bfloat16* __restrict__ xxl)
{
    size_t i = (size_t)blockIdx.x * 256 + threadIdx.x;
    int c = (int)(i & (CC - 1));
    int t = (int)((i >> 9) & (TT - 1));
    float xv = x[i];
    float xp = (t > 0) ? x[i - CC] : 0.f;
    wsplit(fmaf(xp - xv, tmx[c], xv), xxh, xxl, i);
}

// ---------------------------------------------------------------------------
// All weight fp32 -> bf16 hi/lo splits in one launch (grid.y = which weight)
// ---------------------------------------------------------------------------
__global__ void convw_all_kernel(const float* __restrict__ W0, const float* __restrict__ W1,
                                 const float* __restrict__ W2, const float* __restrict__ W3,
                                 const float* __restrict__ W4,
                                 __nv_bfloat16* __restrict__ H0, __nv_bfloat16* __restrict__ L0,
                                 __nv_bfloat16* __restrict__ H1, __nv_bfloat16* __restrict__ L1,
                                 __nv_bfloat16* __restrict__ H2, __nv_bfloat16* __restrict__ L2,
                                 __nv_bfloat16* __restrict__ H3, __nv_bfloat16* __restrict__ L3,
                                 __nv_bfloat16* __restrict__ H4, __nv_bfloat16* __restrict__ L4)
{
    int w = blockIdx.y;
    const float* W = (w == 0) ? W0 : (w == 1) ? W1 : (w == 2) ? W2 : (w == 3) ? W3 : W4;
    __nv_bfloat16* H = (w == 0) ? H0 : (w == 1) ? H1 : (w == 2) ? H2 : (w == 3) ? H3 : H4;
    __nv_bfloat16* L = (w == 0) ? L0 : (w == 1) ? L1 : (w == 2) ? L2 : (w == 3) ? L3 : L4;
    int i = blockIdx.x * 256 + threadIdx.x;
    float v = W[i];
    __nv_bfloat16 h = __float2bfloat16(v);
    H[i] = h;
    L[i] = __float2bfloat16(v - __bfloat162float(h));
}

// ---------------------------------------------------------------------------
// Small-weight transpose + pad + split.
// ---------------------------------------------------------------------------
__global__ void convtd_kernel(const float* __restrict__ tdw1, const float* __restrict__ tdw2,
                              const float* __restrict__ w1, const float* __restrict__ W2,
                              __nv_bfloat16* __restrict__ t1h, __nv_bfloat16* __restrict__ t1l,
                              __nv_bfloat16* __restrict__ t2h, __nv_bfloat16* __restrict__ t2l,
                              __nv_bfloat16* __restrict__ m1h, __nv_bfloat16* __restrict__ m1l,
                              __nv_bfloat16* __restrict__ w2t)
{
    int i = blockIdx.x * 256 + threadIdx.x;
    if (blockIdx.y == 0) {
        if (i < 128 * 512) {
            int n = i >> 9, k = i & 511;
            float v = (n < 64) ? tdw1[(size_t)k * 64 + n] : 0.f;
            wsplit(v, t1h, t1l, i);
        }
    } else if (blockIdx.y == 1) {
        if (i < 512 * 64) {
            int n = i >> 6, k = i & 63;
            float v = tdw2[(size_t)k * 512 + n];
            wsplit(v, t2h, t2l, i);
        }
    } else if (blockIdx.y <= 3) {
        int j = (int)(blockIdx.y - 2) * 81920 + i;
        if (j < 256 * 512) {
            int n = j >> 9, k = j & 511;
            float v = (n < 160) ? w1[(size_t)k * 160 + n] : 0.f;
            wsplit(v, m1h, m1l, j);
        }
    } else {
        if (i < 5 * 512 * 32) {
            int f = i >> 14, rem = i & 16383;
            int c = rem >> 5, dd = rem & 31;
            w2t[i] = __float2bfloat16(W2[(size_t)(f * 32 + dd) * 512 + c]);
        }
    }
}

// ---------------------------------------------------------------------------
// Chunked WKV, kernel 1: per-chunk local scan.
// ---------------------------------------------------------------------------
__global__ void __launch_bounds__(256) wkv_chunk_kernel(
    const float* __restrict__ r, const float* __restrict__ k,
    const float* __restrict__ v, const float* __restrict__ d,
    const float* __restrict__ u,
    float* __restrict__ ylocal, float* __restrict__ Aout,
    float* __restrict__ Lout, float* __restrict__ Pout)
{
    int wid = threadIdx.x >> 5, lane = threadIdx.x & 31;
    int cid = blockIdx.x * 8 + wid;
    int bh = cid >> 4, ch = cid & (NCH - 1);
    int b = bh >> 4, h = bh & (HH - 1);
    size_t base = ((size_t)b * TT + (size_t)ch * CHL) * CC + h * HSZ + lane;

    __shared__ float srkd[8][3][32];

    float S[32];
    #pragma unroll
    for (int j = 0; j < 32; ++j) S[j] = 0.f;
    float P = 1.f;
    float ul = u[h * HSZ + lane];

    size_t off = base;
    float rl = r[off], kl = k[off], dl = d[off], vl = v[off];

    for (int t = 0; t < CHL; ++t) {
        int tn = (t + 1 < CHL) ? (t + 1) : t;
        size_t offn = base + (size_t)tn * CC;
        float rn = r[offn], kn = k[offn], dn = d[offn], vn = v[offn];

        Aout[off] = rl * P;
        P *= dl;

        srkd[wid][0][lane] = rl;
        srkd[wid][1][lane] = kl;
        srkd[wid][2][lane] = dl;
        __syncwarp();

        float cp = rl * ul * kl;
        #pragma unroll
        for (int o = 16; o; o >>= 1) cp += __shfl_xor_sync(0xffffffffu, cp, o);

        float y0 = 0.f, y1 = 0.f, y2 = 0.f, y3 = 0.f;
        #pragma unroll
        for (int j4 = 0; j4 < 8; ++j4) {
            float4 r4 = *reinterpret_cast<const float4*>(&srkd[wid][0][j4 * 4]);
            float4 k4 = *reinterpret_cast<const float4*>(&srkd[wid][1][j4 * 4]);
            float4 d4 = *reinterpret_cast<const float4*>(&srkd[wid][2][j4 * 4]);
            y0 = fmaf(r4.x, S[j4*4+0], y0); S[j4*4+0] = fmaf(d4.x, S[j4*4+0], k4.x * vl);
            y1 = fmaf(r4.y, S[j4*4+1], y1); S[j4*4+1] = fmaf(d4.y, S[j4*4+1], k4.y * vl);
            y2 = fmaf(r4.z, S[j4*4+2], y2); S[j4*4+2] = fmaf(d4.z, S[j4*4+2], k4.z * vl);
            y3 = fmaf(r4.w, S[j4*4+3], y3); S[j4*4+3] = fmaf(d4.w, S[j4*4+3], k4.w * vl);
        }
        ylocal[off] = (y0 + y1) + (y2 + y3) + cp * vl;
        __syncwarp();

        rl = rn; kl = kn; dl = dn; vl = vn;
        off += CC;
    }

    #pragma unroll
    for (int j = 0; j < 32; ++j)
        Lout[(size_t)cid * 1024 + j * 32 + lane] = S[j];
    Pout[(size_t)cid * 32 + lane] = P;
}

// ---------------------------------------------------------------------------
// Chunked WKV, kernel 2: scan chunk states across the sequence.
// ---------------------------------------------------------------------------
__global__ void __launch_bounds__(1024) wkv_state_scan_kernel(
    const float* __restrict__ L, const float* __restrict__ P,
    float* __restrict__ S0out)
{
    int bh = blockIdx.x;
    int e = threadIdx.x;
    int j = e >> 5;
    float s = 0.f;
    #pragma unroll
    for (int c = 0; c < NCH; ++c) {
        size_t cid = (size_t)bh * NCH + c;
        S0out[cid * 1024 + e] = s;
        s = P[cid * 32 + j] * s + L[cid * 1024 + e];
    }
}

// ---------------------------------------------------------------------------
// Chunked WKV, kernel 3 + fused groupnorm * ln * gate -> bf16 hi/lo.
// ---------------------------------------------------------------------------
__global__ void __launch_bounds__(256) wkv_apply_gn_kernel(
    const float* __restrict__ ylocal, const float* __restrict__ A,
    const float* __restrict__ S0, const float* __restrict__ gate,
    const float* __restrict__ lnw, const float* __restrict__ lnb,
    __nv_bfloat16* __restrict__ zh, __nv_bfloat16* __restrict__ zl)
{
    int cid = blockIdx.x;
    int ch = cid & (NCH - 1);
    int bh = cid >> 4;
    int b = bh >> 4, h = bh & (HH - 1);
    int wid = threadIdx.x >> 5, lane = threadIdx.x & 31;

    __shared__ float s0[1024];
    __shared__ float sa[8][32];
    if (ch != 0) {
        for (int i = threadIdx.x; i < 1024; i += 256)
            s0[i] = S0[(size_t)cid * 1024 + i];
    }
    __syncthreads();

    float lw = lnw[h * HSZ + lane];
    float lb = lnb[h * HSZ + lane];

    size_t base = ((size_t)b * TT + (size_t)ch * CHL) * CC + h * HSZ + lane;
    for (int tt = 0; tt < 16; ++tt) {
        int t = wid * 16 + tt;
        size_t off = base + (size_t)t * CC;
        float yv = ylocal[off];
        if (ch != 0) {
            sa[wid][lane] = A[off];
            __syncwarp();
            float acc = 0.f;
            #pragma unroll
            for (int j4 = 0; j4 < 8; ++j4) {
                float4 a4 = *reinterpret_cast<const float4*>(&sa[wid][j4 * 4]);
                acc = fmaf(a4.x, s0[(j4*4+0)*32 + lane], acc);
                acc = fmaf(a4.y, s0[(j4*4+1)*32 + lane], acc);
                acc = fmaf(a4.z, s0[(j4*4+2)*32 + lane], acc);
                acc = fmaf(a4.w, s0[(j4*4+3)*32 + lane], acc);
            }
            yv += acc;
            __syncwarp();
        }
        float s = yv;
        #pragma unroll
        for (int o = 16; o; o >>= 1) s += __shfl_xor_sync(0xffffffffu, s, o);
        float mu = s * (1.f / 32.f);
        float dv = yv - mu;
        float q = dv * dv;
        #pragma unroll
        for (int o = 16; o; o >>= 1) q += __shfl_xor_sync(0xffffffffu, q, o);
        float yn = dv * rsqrtf(q * (1.f / 32.f) + 1e-5f);
        float z = (yn * lw + lb) * gate[off];
        wsplit(z, zh, zl, off);
    }
}

// ---------------------------------------------------------------------------
extern "C" void kernel_launch(void* const* d_in, const int* in_sizes, int n_in,
                              void* d_out, int out_size) {
    const float* x      = (const float*)d_in[0];
    const float* tmaa_x = (const float*)d_in[1];
    const float* tmaa_w = (const float*)d_in[2];
    const float* tmaa_k = (const float*)d_in[3];
    const float* tmaa_v = (const float*)d_in[4];
    const float* tmaa_r = (const float*)d_in[5];
    const float* tmaa_g = (const float*)d_in[6];
    const float* w1     = (const float*)d_in[7];   // (C,160)
    const float* w2     = (const float*)d_in[8];   // (5,32,C)
    const float* tdecay = (const float*)d_in[9];   // (C,)
    const float* tdw1   = (const float*)d_in[10];  // (C,64)
    const float* tdw2   = (const float*)d_in[11];  // (64,C)
    const float* faaaa  = (const float*)d_in[12];  // (H,HS)
    const float* Wr     = (const float*)d_in[13];
    const float* Wk     = (const float*)d_in[14];
    const float* Wv     = (const float*)d_in[15];
    const float* Wg     = (const float*)d_in[16];
    const float* Wo     = (const float*)d_in[17];
    const float* lnw    = (const float*)d_in[18];
    const float* lnb    = (const float*)d_in[19];
    float* out = (float*)d_out;

    unsigned char* S;
    cudaGetSymbolAddress((void**)&S, g_scratch);
    __nv_bfloat16* mixbh = (__nv_bfloat16*)(S + O_MIX);   // bf16 (BT,160)
    float* db   = (float*)(S + O_DB);
    float* rb   = (float*)(S + O_RB);
    float* kb   = (float*)(S + O_KB);
    float* vb   = (float*)(S + O_VB);
    float* gb   = (float*)(S + O_GB);
    float* yb   = (float*)(S + O_YB);
    float* ab   = (float*)(S + O_AB);
    float* lb   = (float*)(S + O_LB);
    float* pb   = (float*)(S + O_PB);
    float* s0b  = (float*)(S + O_S0);
    __nv_bfloat16* xwh = (__nv_bfloat16*)(S + O_XWH);
    __nv_bfloat16* xwl = (__nv_bfloat16*)(S + O_XWL);
    __nv_bfloat16* w64h = (__nv_bfloat16*)(S + O_W64H);
    __nv_bfloat16* w64l = (__nv_bfloat16*)(S + O_W64L);
    __nv_bfloat16* kh = (__nv_bfloat16*)(S + O_KH);
    __nv_bfloat16* kl = (__nv_bfloat16*)(S + O_KL);
    __nv_bfloat16* vh = (__nv_bfloat16*)(S + O_VH);
    __nv_bfloat16* vl = (__nv_bfloat16*)(S + O_VL);
    __nv_bfloat16* rh = (__nv_bfloat16*)(S + O_RH);
    __nv_bfloat16* rl = (__nv_bfloat16*)(S + O_RL);
    __nv_bfloat16* gh = (__nv_bfloat16*)(S + O_GH);
    __nv_bfloat16* gl = (__nv_bfloat16*)(S + O_GL);
    __nv_bfloat16* zh = (__nv_bfloat16*)(S + O_ZH);
    __nv_bfloat16* zl = (__nv_bfloat16*)(S + O_ZL);
    __nv_bfloat16* xxh = (__nv_bfloat16*)(S + O_XXH);
    __nv_bfloat16* xxl = (__nv_bfloat16*)(S + O_XXL);
    __nv_bfloat16* wrh = (__nv_bfloat16*)(S + O_WRH);
    __nv_bfloat16* wrl = (__nv_bfloat16*)(S + O_WRL);
    __nv_bfloat16* wkh = (__nv_bfloat16*)(S + O_WKH);
    __nv_bfloat16* wkl = (__nv_bfloat16*)(S + O_WKL);
    __nv_bfloat16* wvh = (__nv_bfloat16*)(S + O_WVH);
    __nv_bfloat16* wvl = (__nv_bfloat16*)(S + O_WVL);
    __nv_bfloat16* wgh = (__nv_bfloat16*)(S + O_WGH);
    __nv_bfloat16* wgl = (__nv_bfloat16*)(S + O_WGL);
    __nv_bfloat16* woh = (__nv_bfloat16*)(S + O_WOH);
    __nv_bfloat16* wol = (__nv_bfloat16*)(S + O_WOL);
    __nv_bfloat16* t1h = (__nv_bfloat16*)(S + O_T1H);
    __nv_bfloat16* t1l = (__nv_bfloat16*)(S + O_T1L);
    __nv_bfloat16* t2h = (__nv_bfloat16*)(S + O_T2H);
    __nv_bfloat16* t2l = (__nv_bfloat16*)(S + O_T2L);
    __nv_bfloat16* m1h = (__nv_bfloat16*)(S + O_M1H);
    __nv_bfloat16* m1l = (__nv_bfloat16*)(S + O_M1L);
    __nv_bfloat16* mixp = (__nv_bfloat16*)(S + O_MIXP);
    __nv_bfloat16* w2t  = (__nv_bfloat16*)(S + O_W2T);

    cudaFuncSetAttribute(tgemm_kernel<true, 0>, cudaFuncAttributeMaxDynamicSharedMemorySize, TG_SMEM);
    cudaFuncSetAttribute(tgemm_kernel<false, 0>, cudaFuncAttributeMaxDynamicSharedMemorySize, TG_SMEM);
    cudaFuncSetAttribute(tgemm2_kernel<16, 1, 1>, cudaFuncAttributeMaxDynamicSharedMemorySize, TG_SMEM);
    cudaFuncSetAttribute(tgemm2_kernel<2, 3, 0>, cudaFuncAttributeMaxDynamicSharedMemorySize, TG_SMEM);
    cudaFuncSetAttribute(tgemm2_kernel<16, 1, 2>, cudaFuncAttributeMaxDynamicSharedMemorySize, TG_SMEM);

    // 0) weight splits
    convw_all_kernel<<<dim3(1024, 5), 256>>>(Wr, Wk, Wv, Wg, Wo,
                                             wrh, wrl, wkh, wkl, wvh, wvl,
                                             wgh, wgl, woh, wol);
    convtd_kernel<<<dim3(320, 5), 256>>>(tdw1, tdw2, w1, w2,
                                         t1h, t1l, t2h, t2l, m1h, m1l, w2t);

    // 1) xxx = x + (shift(x)-x)*maa_x -> bf16 split
    prep_split_kernel<<<(int)(UEL / 256), 256>>>(x, tmaa_x, xxh, xxl);

    // 2) mix = tanh(xxx @ w1)  [BT,160] on tensor cores, bf16 out
    tgemm2_kernel<16, 1, 2><<<dim3(2, BT / 128), 256, TG_SMEM>>>(
        xxh, xxl, m1h, m1l, nullptr, mixbh, nullptr, nullptr, 160);

    // 3a) back-projection GEMMs: mixproj_f = mix_f @ W2T[f]  (batched over f)
    tgemm3_kernel<<<dim3(4, BT / 128, 5), 256>>>(mixbh, w2t, mixp);

    // 3b) elementwise 5-way token mixing -> bf16 hi/lo operands
    mixapply_kernel<<<(int)(UEL / 1024), 256>>>(x, mixp, tmaa_w, tmaa_k, tmaa_v,
                                                tmaa_r, tmaa_g, xwh, xwl, kh, kl,
                                                vh, vl, rh, rl, gh, gl);

    // 4) 4 projections in ONE batched tensor-core launch (z==3 (g) = silu)
    {
        TGBatch bt_{};
        bt_.ah[0] = rh; bt_.al[0] = rl; bt_.bh[0] = wrh; bt_.bl[0] = wrl; bt_.c[0] = rb;
        bt_.ah[1] = kh; bt_.al[1] = kl; bt_.bh[1] = wkh; bt_.bl[1] = wkl; bt_.c[1] = kb;
        bt_.ah[2] = vh; bt_.al[2] = vl; bt_.bh[2] = wvh; bt_.bl[2] = wvl; bt_.c[2] = vb;
        bt_.ah[3] = gh; bt_.al[3] = gl; bt_.bh[3] = wgh; bt_.bl[3] = wgl; bt_.c[3] = gb;
        tgemm_kernel<true, 0><<<dim3(4, BT / 128, 4), 256, TG_SMEM>>>(
            bt_, nullptr, nullptr, nullptr, nullptr, nullptr);
    }

    // 5) decay MLP on tensor cores
    tgemm2_kernel<16, 1, 1><<<dim3(1, BT / 128), 256, TG_SMEM>>>(
        xwh, xwl, t1h, t1l, nullptr, w64h, w64l, nullptr, 64);
    tgemm2_kernel<2, 3, 0><<<dim3(4, BT / 128), 256, TG_SMEM>>>(
        w64h, w64l, t2h, t2l, db, nullptr, nullptr, tdecay, 512);

    // 6) WKV6 chunked scan: local scans -> state scan -> correction + gn fused
    wkv_chunk_kernel<<<NCID / 8, 256>>>(rb, kb, vb, db, faaaa, yb, ab, lb, pb);
    wkv_state_scan_kernel<<<BQ * HH, 1024>>>(lb, pb, s0b);
    wkv_apply_gn_kernel<<<NCID, 256>>>(yb, ab, s0b, gb, lnw, lnb, zh, zl);

    // 7) out = z @ Wo^T (tensor cores)
    {
        TGBatch dummy{};
        tgemm_kernel<false, 0><<<dim3(4, BT / 128), 256, TG_SMEM>>>(
            dummy, zh, zl, woh, wol, out);
    }
}

// round 14
// speedup vs baseline: 1.4817x; 1.4817x over previous
#include <cuda_runtime.h>
#include <cuda_bf16.h>
#include <cstdint>

#define BQ 8
#define TT 2048
#define CC 512
#define HH 16
#define HSZ 32
#define BT (BQ*TT)            // 16384
#define UEL ((size_t)BT*CC)   // 8388608 elements per [B,T,C] buffer
#define NCH 16                // chunks per sequence
#define CHL 128               // chunk length (TT/NCH)
#define NCID (BQ*HH*NCH)      // 2048 total chunks

// ---------------------------------------------------------------------------
// Scratch (bytes). One big device array; no allocations anywhere.
// ---------------------------------------------------------------------------
#define SZ_F32   (UEL*4)
#define SZ_BF16  (UEL*2)
#define SZ_MIX   ((size_t)BT*160*4)
#define SZ_W64B  ((size_t)BT*64*2)
#define SZ_WBF   ((size_t)CC*CC*2)
#define SZ_L     ((size_t)NCID*1024*4)
#define SZ_P     ((size_t)NCID*32*4)

#define O_MIX   ((size_t)0)
#define O_XWH   (O_MIX + SZ_MIX)
#define O_XWL   (O_XWH + SZ_BF16)
#define O_W64H  (O_XWL + SZ_BF16)
#define O_W64L  (O_W64H + SZ_W64B)
#define O_DB    (O_W64L + SZ_W64B)
#define O_RB    (O_DB + SZ_F32)
#define O_KB    (O_RB + SZ_F32)
#define O_VB    (O_KB + SZ_F32)
#define O_GB    (O_VB + SZ_F32)
#define O_YB    (O_GB + SZ_F32)
#define O_AB    (O_YB + SZ_F32)
#define O_LB    (O_AB + SZ_F32)
#define O_PB    (O_LB + SZ_L)
#define O_S0    (O_PB + SZ_P)
#define O_KH    (O_S0 + SZ_L)
#define O_KL    (O_KH + SZ_BF16)
#define O_VH    (O_KL + SZ_BF16)
#define O_VL    (O_VH + SZ_BF16)
#define O_RH    (O_VL + SZ_BF16)
#define O_RL    (O_RH + SZ_BF16)
#define O_GH    (O_RL + SZ_BF16)
#define O_GL    (O_GH + SZ_BF16)
#define O_ZH    (O_GL + SZ_BF16)
#define O_ZL    (O_ZH + SZ_BF16)
#define O_XXH   (O_ZL + SZ_BF16)
#define O_XXL   (O_XXH + SZ_BF16)
#define O_WRH   (O_XXL + SZ_BF16)
#define O_WRL   (O_WRH + SZ_WBF)
#define O_WKH   (O_WRL + SZ_WBF)
#define O_WKL   (O_WKH + SZ_WBF)
#define O_WVH   (O_WKL + SZ_WBF)
#define O_WVL   (O_WVH + SZ_WBF)
#define O_WGH   (O_WVL + SZ_WBF)
#define O_WGL   (O_WGH + SZ_WBF)
#define O_WOH   (O_WGL + SZ_WBF)
#define O_WOL   (O_WOH + SZ_WBF)
#define O_T1H   (O_WOL + SZ_WBF)                 // tdw1^T padded: 128x512 bf16
#define O_T1L   (O_T1H + (size_t)128*512*2)
#define O_T2H   (O_T1L + (size_t)128*512*2)      // tdw2^T: 512x64 bf16
#define O_T2L   (O_T2H + (size_t)512*64*2)
#define O_M1H   (O_T2L + (size_t)512*64*2)       // w1^T padded: 256x512 bf16
#define O_M1L   (O_M1H + (size_t)256*512*2)
#define O_MIXP  (O_M1L + (size_t)256*512*2)      // 5 planes of (BT,512) bf16
#define O_W2T   (O_MIXP + (size_t)5*UEL*2)       // W2^T: 5 x 512 x 32 bf16
#define SCRATCH_BYTES (O_W2T + (size_t)5*512*32*2)

__device__ __align__(256) unsigned char g_scratch[SCRATCH_BYTES];

// ---------------------------------------------------------------------------
// mma.sync / cp.async helpers (valid on plain compute_103 / sm_80+)
// ---------------------------------------------------------------------------
__device__ __forceinline__ uint32_t smem_u32(const void* p) {
    uint32_t a;
    asm("{ .reg .u64 t; cvta.to.shared.u64 t, %1; cvt.u32.u64 %0, t; }"
        : "=r"(a) : "l"(p));
    return a;
}

#define LDSM4(r, a) \
    asm volatile("ldmatrix.sync.aligned.m8n8.x4.shared.b16 {%0,%1,%2,%3}, [%4];" \
        : "=r"((r)[0]), "=r"((r)[1]), "=r"((r)[2]), "=r"((r)[3]) : "r"(a))

#define MMA16816(d, a, b0, b1) \
    asm volatile("mma.sync.aligned.m16n8k16.row.col.f32.bf16.bf16.f32 " \
        "{%0,%1,%2,%3}, {%4,%5,%6,%7}, {%8,%9}, {%0,%1,%2,%3};" \
        : "+f"((d)[0]), "+f"((d)[1]), "+f"((d)[2]), "+f"((d)[3]) \
        : "r"((a)[0]), "r"((a)[1]), "r"((a)[2]), "r"((a)[3]), "r"(b0), "r"(b1))

#define CP_ASYNC16(dst, src) \
    asm volatile("cp.async.cg.shared.global [%0], [%1], 16;" :: "r"(dst), "l"(src))
#define CP_COMMIT() asm volatile("cp.async.commit_group;" ::: "memory")
#define CP_WAIT(n)  asm volatile("cp.async.wait_group %0;" :: "n"(n) : "memory")

#define TROWB 80
#define TTILE (128*TROWB)     // 10240
#define TSTAGE (4*TTILE)      // 40960
#define TG_SMEM (2*TSTAGE)    // 81920
#define ROWSKIP (64*1024)     // 64 rows * 512 cols * 2B (K=512 path)
#define DSTSKIP (64*TROWB)

// ---------------------------------------------------------------------------
// split / pack helpers
// ---------------------------------------------------------------------------
__device__ __forceinline__ void wsplit(float v, __nv_bfloat16* hi, __nv_bfloat16* lo, size_t i) {
    __nv_bfloat16 h = __float2bfloat16(v);
    hi[i] = h;
    lo[i] = __float2bfloat16(v - __bfloat162float(h));
}
__device__ __forceinline__ uint32_t pack_bf2(float a, float b) {
    __nv_bfloat162 p;
    p.x = __float2bfloat16(a);
    p.y = __float2bfloat16(b);
    return *reinterpret_cast<uint32_t*>(&p);
}

// ---------------------------------------------------------------------------
// Pipelined tensor-core GEMM (hot path, K=512, N=512): R12 schedule.
// ---------------------------------------------------------------------------
struct TGBatch {
    const __nv_bfloat16 *ah[4], *al[4], *bh[4], *bl[4];
    float* c[4];
};

template<bool BATCH, int EPI>
__global__ void __launch_bounds__(256, 2)
tgemm_kernel(TGBatch bt_,
             const __nv_bfloat16* __restrict__ Ah_, const __nv_bfloat16* __restrict__ Al_,
             const __nv_bfloat16* __restrict__ Bh_, const __nv_bfloat16* __restrict__ Bl_,
             float* __restrict__ C_)
{
    extern __shared__ unsigned char sm[];
    uint32_t smb = smem_u32(sm);
    int tid = threadIdx.x;
    int wid = tid >> 5, lane = tid & 31;
    int bm = blockIdx.y * 128, bn = blockIdx.x * 128;
    int wm = (wid & 3) * 32, wn = (wid >> 2) * 64;

    int z = BATCH ? blockIdx.z : 0;
    const __nv_bfloat16* Ah = BATCH ? bt_.ah[z] : Ah_;
    const __nv_bfloat16* Al = BATCH ? bt_.al[z] : Al_;
    const __nv_bfloat16* Bh = BATCH ? bt_.bh[z] : Bh_;
    const __nv_bfloat16* Bl = BATCH ? bt_.bl[z] : Bl_;
    float* C = BATCH ? bt_.c[z] : C_;
    bool do_silu = BATCH ? (z == 3) : (EPI == 2);

    int rowq = tid >> 2;
    int gcol = (tid & 3) * 8;
    const char* pAh = (const char*)(Ah + (size_t)(bm + rowq) * 512 + gcol);
    const char* pAl = (const char*)(Al + (size_t)(bm + rowq) * 512 + gcol);
    const char* pBh = (const char*)(Bh + (size_t)(bn + rowq) * 512 + gcol);
    const char* pBl = (const char*)(Bl + (size_t)(bn + rowq) * 512 + gcol);
    uint32_t dA = smb + rowq * TROWB + (tid & 3) * 16;
    uint32_t dB = dA + 2 * TTILE;

    float acc[2][8][4];
    #pragma unroll
    for (int i = 0; i < 2; ++i)
        #pragma unroll
        for (int j = 0; j < 8; ++j)
            #pragma unroll
            for (int q = 0; q < 4; ++q) acc[i][j][q] = 0.f;

    int mat = lane >> 3, r8 = lane & 7;
    int lrow = (mat & 1) * 8 + r8;
    int lkb  = (mat >> 1) * 16;
    uint32_t raBase = smb + (wm + lrow) * TROWB + lkb;
    uint32_t rbBase = smb + 2 * TTILE + (wn + lrow) * TROWB + lkb;

    {
        CP_ASYNC16(dA,                    pAh);
        CP_ASYNC16(dA + DSTSKIP,          pAh + ROWSKIP);
        CP_ASYNC16(dA + TTILE,            pAl);
        CP_ASYNC16(dA + TTILE + DSTSKIP,  pAl + ROWSKIP);
        CP_ASYNC16(dB,                    pBh);
        CP_ASYNC16(dB + DSTSKIP,          pBh + ROWSKIP);
        CP_ASYNC16(dB + TTILE,            pBl);
        CP_ASYNC16(dB + TTILE + DSTSKIP,  pBl + ROWSKIP);
        pAh += 64; pAl += 64; pBh += 64; pBl += 64;
        CP_COMMIT();
    }

    for (int ch = 0; ch < 16; ++ch) {
        if (ch + 1 < 16) {
            uint32_t so = ((ch + 1) & 1) * TSTAGE;
            CP_ASYNC16(dA + so,                    pAh);
            CP_ASYNC16(dA + so + DSTSKIP,          pAh + ROWSKIP);
            CP_ASYNC16(dA + so + TTILE,            pAl);
            CP_ASYNC16(dA + so + TTILE + DSTSKIP,  pAl + ROWSKIP);
            CP_ASYNC16(dB + so,                    pBh);
            CP_ASYNC16(dB + so + DSTSKIP,          pBh + ROWSKIP);
            CP_ASYNC16(dB + so + TTILE,            pBl);
            CP_ASYNC16(dB + so + TTILE + DSTSKIP,  pBl + ROWSKIP);
            pAh += 64; pAl += 64; pBh += 64; pBl += 64;
            CP_COMMIT();
            CP_WAIT(1);
        } else {
            CP_WAIT(0);
        }
        __syncthreads();

        uint32_t so = (ch & 1) * TSTAGE;
        uint32_t ra0 = raBase + so;
        uint32_t rb0 = rbBase + so;
        #pragma unroll
        for (int ks = 0; ks < 2; ++ks) {
            uint32_t ah[2][4], al[2][4];
            #pragma unroll
            for (int mt = 0; mt < 2; ++mt) {
                uint32_t ra = ra0 + mt * (16 * TROWB) + ks * 32;
                LDSM4(ah[mt], ra);
                LDSM4(al[mt], ra + TTILE);
            }
            #pragma unroll
            for (int nt = 0; nt < 4; ++nt) {
                uint32_t rb = rb0 + nt * (16 * TROWB) + ks * 32;
                uint32_t bh4[4], bl4[4];
                LDSM4(bh4, rb);
                LDSM4(bl4, rb + TTILE);
                #pragma unroll
                for (int mt = 0; mt < 2; ++mt) {
                    MMA16816(acc[mt][nt*2+0], ah[mt], bh4[0], bh4[2]);
                    MMA16816(acc[mt][nt*2+1], ah[mt], bh4[1], bh4[3]);
                    MMA16816(acc[mt][nt*2+0], ah[mt], bl4[0], bl4[2]);
                    MMA16816(acc[mt][nt*2+1], ah[mt], bl4[1], bl4[3]);
                    MMA16816(acc[mt][nt*2+0], al[mt], bh4[0], bh4[2]);
                    MMA16816(acc[mt][nt*2+1], al[mt], bh4[1], bh4[3]);
                }
            }
        }
        __syncthreads();
    }

    int r0 = lane >> 2, c0 = (lane & 3) * 2;
    #pragma unroll
    for (int mt = 0; mt < 2; ++mt) {
        #pragma unroll
        for (int nt = 0; nt < 4; ++nt) {
            #pragma unroll
            for (int s = 0; s < 2; ++s) {
                float* a4 = acc[mt][nt*2+s];
                int col = bn + wn + nt * 16 + s * 8 + c0;
                int row = bm + wm + mt * 16 + r0;
                float v0 = a4[0], v1 = a4[1], v2 = a4[2], v3 = a4[3];
                if (do_silu) {
                    v0 = v0 / (1.f + __expf(-v0));
                    v1 = v1 / (1.f + __expf(-v1));
                    v2 = v2 / (1.f + __expf(-v2));
                    v3 = v3 / (1.f + __expf(-v3));
                }
                *reinterpret_cast<float2*>(C + (size_t)row * 512 + col)       = make_float2(v0, v1);
                *reinterpret_cast<float2*>(C + (size_t)(row + 8) * 512 + col) = make_float2(v2, v3);
            }
        }
    }
}

// ---------------------------------------------------------------------------
// Parameterized tensor GEMM (decay MLP + mix GEMM). R12 schedule.
// NK = K/32 chunks. EPI: 1 tanh, 3 exp(-exp(bias+v)).
// OM: 0 fp32 out, 1 split bf16 hi/lo out, 2 single bf16 out.
// ---------------------------------------------------------------------------
template<int NK, int EPI, int OM>
__global__ void __launch_bounds__(256, 2)
tgemm2_kernel(const __nv_bfloat16* __restrict__ Ah, const __nv_bfloat16* __restrict__ Al,
              const __nv_bfloat16* __restrict__ Bh, const __nv_bfloat16* __restrict__ Bl,
              float* __restrict__ Cf,
              __nv_bfloat16* __restrict__ Chi, __nv_bfloat16* __restrict__ Clo,
              const float* __restrict__ bias, int N)
{
    constexpr int K = NK * 32;
    constexpr int RSKIP = 64 * K * 2;
    extern __shared__ unsigned char sm[];
    uint32_t smb = smem_u32(sm);
    int tid = threadIdx.x;
    int wid = tid >> 5, lane = tid & 31;
    int bm = blockIdx.y * 128, bn = blockIdx.x * 128;
    int wm = (wid & 3) * 32, wn = (wid >> 2) * 64;

    int rowq = tid >> 2;
    int gcol = (tid & 3) * 8;
    const char* pAh = (const char*)(Ah + (size_t)(bm + rowq) * K + gcol);
    const char* pAl = (const char*)(Al + (size_t)(bm + rowq) * K + gcol);
    const char* pBh = (const char*)(Bh + (size_t)(bn + rowq) * K + gcol);
    const char* pBl = (const char*)(Bl + (size_t)(bn + rowq) * K + gcol);
    uint32_t dA = smb + rowq * TROWB + (tid & 3) * 16;
    uint32_t dB = dA + 2 * TTILE;

    float acc[2][8][4];
    #pragma unroll
    for (int i = 0; i < 2; ++i)
        #pragma unroll
        for (int j = 0; j < 8; ++j)
            #pragma unroll
            for (int q = 0; q < 4; ++q) acc[i][j][q] = 0.f;

    int mat = lane >> 3, r8 = lane & 7;
    int lrow = (mat & 1) * 8 + r8;
    int lkb  = (mat >> 1) * 16;
    uint32_t raBase = smb + (wm + lrow) * TROWB + lkb;
    uint32_t rbBase = smb + 2 * TTILE + (wn + lrow) * TROWB + lkb;

    {
        CP_ASYNC16(dA,                   pAh);
        CP_ASYNC16(dA + DSTSKIP,         pAh + RSKIP);
        CP_ASYNC16(dA + TTILE,           pAl);
        CP_ASYNC16(dA + TTILE + DSTSKIP, pAl + RSKIP);
        CP_ASYNC16(dB,                   pBh);
        CP_ASYNC16(dB + DSTSKIP,         pBh + RSKIP);
        CP_ASYNC16(dB + TTILE,           pBl);
        CP_ASYNC16(dB + TTILE + DSTSKIP, pBl + RSKIP);
        pAh += 64; pAl += 64; pBh += 64; pBl += 64;
        CP_COMMIT();
    }

    for (int ch = 0; ch < NK; ++ch) {
        if (ch + 1 < NK) {
            uint32_t so = ((ch + 1) & 1) * TSTAGE;
            CP_ASYNC16(dA + so,                   pAh);
            CP_ASYNC16(dA + so + DSTSKIP,         pAh + RSKIP);
            CP_ASYNC16(dA + so + TTILE,           pAl);
            CP_ASYNC16(dA + so + TTILE + DSTSKIP, pAl + RSKIP);
            CP_ASYNC16(dB + so,                   pBh);
            CP_ASYNC16(dB + so + DSTSKIP,         pBh + RSKIP);
            CP_ASYNC16(dB + so + TTILE,           pBl);
            CP_ASYNC16(dB + so + TTILE + DSTSKIP, pBl + RSKIP);
            pAh += 64; pAl += 64; pBh += 64; pBl += 64;
            CP_COMMIT();
            CP_WAIT(1);
        } else {
            CP_WAIT(0);
        }
        __syncthreads();

        uint32_t so = (ch & 1) * TSTAGE;
        uint32_t ra0 = raBase + so;
        uint32_t rb0 = rbBase + so;
        #pragma unroll
        for (int ks = 0; ks < 2; ++ks) {
            uint32_t ah[2][4], al[2][4];
            #pragma unroll
            for (int mt = 0; mt < 2; ++mt) {
                uint32_t ra = ra0 + mt * (16 * TROWB) + ks * 32;
                LDSM4(ah[mt], ra);
                LDSM4(al[mt], ra + TTILE);
            }
            #pragma unroll
            for (int nt = 0; nt < 4; ++nt) {
                uint32_t rb = rb0 + nt * (16 * TROWB) + ks * 32;
                uint32_t bh4[4], bl4[4];
                LDSM4(bh4, rb);
                LDSM4(bl4, rb + TTILE);
                #pragma unroll
                for (int mt = 0; mt < 2; ++mt) {
                    MMA16816(acc[mt][nt*2+0], ah[mt], bh4[0], bh4[2]);
                    MMA16816(acc[mt][nt*2+1], ah[mt], bh4[1], bh4[3]);
                    MMA16816(acc[mt][nt*2+0], ah[mt], bl4[0], bl4[2]);
                    MMA16816(acc[mt][nt*2+1], ah[mt], bl4[1], bl4[3]);
                    MMA16816(acc[mt][nt*2+0], al[mt], bh4[0], bh4[2]);
                    MMA16816(acc[mt][nt*2+1], al[mt], bh4[1], bh4[3]);
                }
            }
        }
        __syncthreads();
    }

    int r0 = lane >> 2, c0 = (lane & 3) * 2;
    #pragma unroll
    for (int mt = 0; mt < 2; ++mt) {
        #pragma unroll
        for (int nt = 0; nt < 4; ++nt) {
            #pragma unroll
            for (int s = 0; s < 2; ++s) {
                float* a4 = acc[mt][nt*2+s];
                int col = bn + wn + nt * 16 + s * 8 + c0;
                if (col >= N) continue;
                int row = bm + wm + mt * 16 + r0;
                #pragma unroll
                for (int half = 0; half < 2; ++half) {
                    float v0 = a4[half * 2 + 0], v1 = a4[half * 2 + 1];
                    size_t ro = (size_t)(row + half * 8) * N + col;
                    if (EPI == 1) { v0 = tanhf(v0); v1 = tanhf(v1); }
                    else if (EPI == 3) {
                        v0 = __expf(-__expf(bias[col] + v0));
                        v1 = __expf(-__expf(bias[col + 1] + v1));
                    }
                    if (OM == 1) {
                        wsplit(v0, Chi, Clo, ro);
                        wsplit(v1, Chi, Clo, ro + 1);
                    } else if (OM == 2) {
                        *reinterpret_cast<uint32_t*>(Chi + ro) = pack_bf2(v0, v1);
                    } else {
                        *reinterpret_cast<float2*>(Cf + ro) = make_float2(v0, v1);
                    }
                }
            }
        }
    }
}

// ---------------------------------------------------------------------------
// Mix back-projection GEMM: mixproj_f = mix[:, f*32:(f+1)*32] @ W2T[f]
// ---------------------------------------------------------------------------
__global__ void __launch_bounds__(256)
tgemm3_kernel(const __nv_bfloat16* __restrict__ mixbh,
              const __nv_bfloat16* __restrict__ w2t,
              __nv_bfloat16* __restrict__ mixp)
{
    __shared__ unsigned char sm3[2 * TTILE];
    uint32_t smb = smem_u32(sm3);
    int tid = threadIdx.x;
    int wid = tid >> 5, lane = tid & 31;
    int bn = blockIdx.x * 128, bm = blockIdx.y * 128, f = blockIdx.z;
    int wm = (wid & 3) * 32, wn = (wid >> 2) * 64;

    #pragma unroll
    for (int q = 0; q < 2; ++q) {
        int e = tid * 2 + q;           // 0..511
        int row = e >> 2, g = e & 3;
        CP_ASYNC16(smb + row * TROWB + g * 16,
                   mixbh + (size_t)(bm + row) * 160 + f * 32 + g * 8);
        CP_ASYNC16(smb + TTILE + row * TROWB + g * 16,
                   w2t + (size_t)f * 512 * 32 + (size_t)(bn + row) * 32 + g * 8);
    }
    CP_COMMIT();
    CP_WAIT(0);
    __syncthreads();

    float acc[2][8][4];
    #pragma unroll
    for (int i = 0; i < 2; ++i)
        #pragma unroll
        for (int j = 0; j < 8; ++j)
            #pragma unroll
            for (int q = 0; q < 4; ++q) acc[i][j][q] = 0.f;

    int mat = lane >> 3, r8 = lane & 7;
    int lrow = (mat & 1) * 8 + r8;
    int lkb  = (mat >> 1) * 16;
    uint32_t ra0 = smb + (wm + lrow) * TROWB + lkb;
    uint32_t rb0 = smb + TTILE + (wn + lrow) * TROWB + lkb;

    #pragma unroll
    for (int ks = 0; ks < 2; ++ks) {
        uint32_t ah[2][4];
        #pragma unroll
        for (int mt = 0; mt < 2; ++mt)
            LDSM4(ah[mt], ra0 + mt * (16 * TROWB) + ks * 32);
        #pragma unroll
        for (int nt = 0; nt < 4; ++nt) {
            uint32_t bh4[4];
            LDSM4(bh4, rb0 + nt * (16 * TROWB) + ks * 32);
            #pragma unroll
            for (int mt = 0; mt < 2; ++mt) {
                MMA16816(acc[mt][nt*2+0], ah[mt], bh4[0], bh4[2]);
                MMA16816(acc[mt][nt*2+1], ah[mt], bh4[1], bh4[3]);
            }
        }
    }

    __nv_bfloat16* Cb = mixp + (size_t)f * UEL;
    int r0 = lane >> 2, c0 = (lane & 3) * 2;
    #pragma unroll
    for (int mt = 0; mt < 2; ++mt) {
        #pragma unroll
        for (int nt = 0; nt < 4; ++nt) {
            #pragma unroll
            for (int s = 0; s < 2; ++s) {
                float* a4 = acc[mt][nt*2+s];
                int col = bn + wn + nt * 16 + s * 8 + c0;
                int row = bm + wm + mt * 16 + r0;
                *reinterpret_cast<uint32_t*>(Cb + (size_t)row * 512 + col)       = pack_bf2(a4[0], a4[1]);
                *reinterpret_cast<uint32_t*>(Cb + (size_t)(row + 8) * 512 + col) = pack_bf2(a4[2], a4[3]);
            }
        }
    }
}

// ---------------------------------------------------------------------------
// Elementwise 5-way token mix apply: x_f = x + (xshift-x)*(maa_f + mixproj_f)
// ---------------------------------------------------------------------------
__global__ void __launch_bounds__(256) mixapply_kernel(
    const float* __restrict__ x, const __nv_bfloat16* __restrict__ mixp,
    const float* __restrict__ maaw, const float* __restrict__ maak,
    const float* __restrict__ maav, const float* __restrict__ maar,
    const float* __restrict__ maag,
    __nv_bfloat16* __restrict__ xwh, __nv_bfloat16* __restrict__ xwl,
    __nv_bfloat16* __restrict__ kh, __nv_bfloat16* __restrict__ kl,
    __nv_bfloat16* __restrict__ vh, __nv_bfloat16* __restrict__ vl,
    __nv_bfloat16* __restrict__ rh, __nv_bfloat16* __restrict__ rl,
    __nv_bfloat16* __restrict__ gh, __nv_bfloat16* __restrict__ gl)
{
    size_t i = ((size_t)blockIdx.x * 256 + threadIdx.x) * 4;
    int c = (int)(i & 511);
    int t = (int)((i >> 9) & (TT - 1));
    float4 xv = *reinterpret_cast<const float4*>(x + i);
    float4 xp = make_float4(0.f, 0.f, 0.f, 0.f);
    if (t) xp = *reinterpret_cast<const float4*>(x + i - 512);
    float xc[4] = {xv.x, xv.y, xv.z, xv.w};
    float xx[4] = {xp.x - xv.x, xp.y - xv.y, xp.z - xv.z, xp.w - xv.w};

    #pragma unroll
    for (int f = 0; f < 5; ++f) {
        const float* maa = (f == 0) ? maaw : (f == 1) ? maak : (f == 2) ? maav
                         : (f == 3) ? maar : maag;
        float4 m4 = *reinterpret_cast<const float4*>(maa + c);
        uint2 mp = *reinterpret_cast<const uint2*>(mixp + (size_t)f * UEL + i);
        __nv_bfloat162 m01 = *reinterpret_cast<__nv_bfloat162*>(&mp.x);
        __nv_bfloat162 m23 = *reinterpret_cast<__nv_bfloat162*>(&mp.y);
        float mv[4] = {__bfloat162float(m01.x), __bfloat162float(m01.y),
                       __bfloat162float(m23.x), __bfloat162float(m23.y)};
        float ma[4] = {m4.x, m4.y, m4.z, m4.w};
        float v[4], h[4];
        #pragma unroll
        for (int e = 0; e < 4; ++e) {
            v[e] = fmaf(xx[e], ma[e] + mv[e], xc[e]);
            h[e] = __bfloat162float(__float2bfloat16(v[e]));
        }
        uint2 hi2, lo2;
        hi2.x = pack_bf2(v[0], v[1]);
        hi2.y = pack_bf2(v[2], v[3]);
        lo2.x = pack_bf2(v[0] - h[0], v[1] - h[1]);
        lo2.y = pack_bf2(v[2] - h[2], v[3] - h[3]);
        __nv_bfloat16* dh = (f == 0) ? xwh : (f == 1) ? kh : (f == 2) ? vh
                          : (f == 3) ? rh : gh;
        __nv_bfloat16* dl = (f == 0) ? xwl : (f == 1) ? kl : (f == 2) ? vl
                          : (f == 3) ? rl : gl;
        *reinterpret_cast<uint2*>(dh + i) = hi2;
        *reinterpret_cast<uint2*>(dl + i) = lo2;
    }
}

// ---------------------------------------------------------------------------
// prep: xxx = x + (xshift - x) * maa_x  -> bf16 hi/lo
// ---------------------------------------------------------------------------
__global__ void __launch_bounds__(256) prep_split_kernel(
    const float* __restrict__ x, const float* __restrict__ tmx,
    __nv_bfloat16* __restrict__ xxh, __nv_bfloat16* __restrict__ xxl)
{
    size_t i = (size_t)blockIdx.x * 256 + threadIdx.x;
    int c = (int)(i & (CC - 1));
    int t = (int)((i >> 9) & (TT - 1));
    float xv = x[i];
    float xp = (t > 0) ? x[i - CC] : 0.f;
    wsplit(fmaf(xp - xv, tmx[c], xv), xxh, xxl, i);
}

// ---------------------------------------------------------------------------
// All weight fp32 -> bf16 hi/lo splits in one launch (grid.y = which weight)
// ---------------------------------------------------------------------------
__global__ void convw_all_kernel(const float* __restrict__ W0, const float* __restrict__ W1,
                                 const float* __restrict__ W2, const float* __restrict__ W3,
                                 const float* __restrict__ W4,
                                 __nv_bfloat16* __restrict__ H0, __nv_bfloat16* __restrict__ L0,
                                 __nv_bfloat16* __restrict__ H1, __nv_bfloat16* __restrict__ L1,
                                 __nv_bfloat16* __restrict__ H2, __nv_bfloat16* __restrict__ L2,
                                 __nv_bfloat16* __restrict__ H3, __nv_bfloat16* __restrict__ L3,
                                 __nv_bfloat16* __restrict__ H4, __nv_bfloat16* __restrict__ L4)
{
    int w = blockIdx.y;
    const float* W = (w == 0) ? W0 : (w == 1) ? W1 : (w == 2) ? W2 : (w == 3) ? W3 : W4;
    __nv_bfloat16* H = (w == 0) ? H0 : (w == 1) ? H1 : (w == 2) ? H2 : (w == 3) ? H3 : H4;
    __nv_bfloat16* L = (w == 0) ? L0 : (w == 1) ? L1 : (w == 2) ? L2 : (w == 3) ? L3 : L4;
    int i = blockIdx.x * 256 + threadIdx.x;
    float v = W[i];
    __nv_bfloat16 h = __float2bfloat16(v);
    H[i] = h;
    L[i] = __float2bfloat16(v - __bfloat162float(h));
}

// ---------------------------------------------------------------------------
// Small-weight transpose + pad + split.
// ---------------------------------------------------------------------------
__global__ void convtd_kernel(const float* __restrict__ tdw1, const float* __restrict__ tdw2,
                              const float* __restrict__ w1, const float* __restrict__ W2,
                              __nv_bfloat16* __restrict__ t1h, __nv_bfloat16* __restrict__ t1l,
                              __nv_bfloat16* __restrict__ t2h, __nv_bfloat16* __restrict__ t2l,
                              __nv_bfloat16* __restrict__ m1h, __nv_bfloat16* __restrict__ m1l,
                              __nv_bfloat16* __restrict__ w2t)
{
    int i = blockIdx.x * 256 + threadIdx.x;
    if (blockIdx.y == 0) {
        if (i < 128 * 512) {
            int n = i >> 9, k = i & 511;
            float v = (n < 64) ? tdw1[(size_t)k * 64 + n] : 0.f;
            wsplit(v, t1h, t1l, i);
        }
    } else if (blockIdx.y == 1) {
        if (i < 512 * 64) {
            int n = i >> 6, k = i & 63;
            float v = tdw2[(size_t)k * 512 + n];
            wsplit(v, t2h, t2l, i);
        }
    } else if (blockIdx.y <= 3) {
        int j = (int)(blockIdx.y - 2) * 81920 + i;
        if (j < 256 * 512) {
            int n = j >> 9, k = j & 511;
            float v = (n < 160) ? w1[(size_t)k * 160 + n] : 0.f;
            wsplit(v, m1h, m1l, j);
        }
    } else {
        if (i < 5 * 512 * 32) {
            int f = i >> 14, rem = i & 16383;
            int c = rem >> 5, dd = rem & 31;
            w2t[i] = __float2bfloat16(W2[(size_t)(f * 32 + dd) * 512 + c]);
        }
    }
}

// ---------------------------------------------------------------------------
// Chunked WKV, kernel 1: per-chunk local scan.
// ---------------------------------------------------------------------------
__global__ void __launch_bounds__(256) wkv_chunk_kernel(
    const float* __restrict__ r, const float* __restrict__ k,
    const float* __restrict__ v, const float* __restrict__ d,
    const float* __restrict__ u,
    float* __restrict__ ylocal, float* __restrict__ Aout,
    float* __restrict__ Lout, float* __restrict__ Pout)
{
    int wid = threadIdx.x >> 5, lane = threadIdx.x & 31;
    int cid = blockIdx.x * 8 + wid;
    int bh = cid >> 4, ch = cid & (NCH - 1);
    int b = bh >> 4, h = bh & (HH - 1);
    size_t base = ((size_t)b * TT + (size_t)ch * CHL) * CC + h * HSZ + lane;

    __shared__ float srkd[8][3][32];

    float S[32];
    #pragma unroll
    for (int j = 0; j < 32; ++j) S[j] = 0.f;
    float P = 1.f;
    float ul = u[h * HSZ + lane];

    size_t off = base;
    float rl = r[off], kl = k[off], dl = d[off], vl = v[off];

    for (int t = 0; t < CHL; ++t) {
        int tn = (t + 1 < CHL) ? (t + 1) : t;
        size_t offn = base + (size_t)tn * CC;
        float rn = r[offn], kn = k[offn], dn = d[offn], vn = v[offn];

        Aout[off] = rl * P;
        P *= dl;

        srkd[wid][0][lane] = rl;
        srkd[wid][1][lane] = kl;
        srkd[wid][2][lane] = dl;
        __syncwarp();

        float cp = rl * ul * kl;
        #pragma unroll
        for (int o = 16; o; o >>= 1) cp += __shfl_xor_sync(0xffffffffu, cp, o);

        float y0 = 0.f, y1 = 0.f, y2 = 0.f, y3 = 0.f;
        #pragma unroll
        for (int j4 = 0; j4 < 8; ++j4) {
            float4 r4 = *reinterpret_cast<const float4*>(&srkd[wid][0][j4 * 4]);
            float4 k4 = *reinterpret_cast<const float4*>(&srkd[wid][1][j4 * 4]);
            float4 d4 = *reinterpret_cast<const float4*>(&srkd[wid][2][j4 * 4]);
            y0 = fmaf(r4.x, S[j4*4+0], y0); S[j4*4+0] = fmaf(d4.x, S[j4*4+0], k4.x * vl);
            y1 = fmaf(r4.y, S[j4*4+1], y1); S[j4*4+1] = fmaf(d4.y, S[j4*4+1], k4.y * vl);
            y2 = fmaf(r4.z, S[j4*4+2], y2); S[j4*4+2] = fmaf(d4.z, S[j4*4+2], k4.z * vl);
            y3 = fmaf(r4.w, S[j4*4+3], y3); S[j4*4+3] = fmaf(d4.w, S[j4*4+3], k4.w * vl);
        }
        ylocal[off] = (y0 + y1) + (y2 + y3) + cp * vl;
        __syncwarp();

        rl = rn; kl = kn; dl = dn; vl = vn;
        off += CC;
    }

    #pragma unroll
    for (int j = 0; j < 32; ++j)
        Lout[(size_t)cid * 1024 + j * 32 + lane] = S[j];
    Pout[(size_t)cid * 32 + lane] = P;
}

// ---------------------------------------------------------------------------
// Chunked WKV, kernel 2: scan chunk states across the sequence.
// ---------------------------------------------------------------------------
__global__ void __launch_bounds__(1024) wkv_state_scan_kernel(
    const float* __restrict__ L, const float* __restrict__ P,
    float* __restrict__ S0out)
{
    int bh = blockIdx.x;
    int e = threadIdx.x;
    int j = e >> 5;
    float s = 0.f;
    #pragma unroll
    for (int c = 0; c < NCH; ++c) {
        size_t cid = (size_t)bh * NCH + c;
        S0out[cid * 1024 + e] = s;
        s = P[cid * 32 + j] * s + L[cid * 1024 + e];
    }
}

// ---------------------------------------------------------------------------
// Chunked WKV, kernel 3 + fused groupnorm * ln * gate -> bf16 hi/lo.
// ---------------------------------------------------------------------------
__global__ void __launch_bounds__(256) wkv_apply_gn_kernel(
    const float* __restrict__ ylocal, const float* __restrict__ A,
    const float* __restrict__ S0, const float* __restrict__ gate,
    const float* __restrict__ lnw, const float* __restrict__ lnb,
    __nv_bfloat16* __restrict__ zh, __nv_bfloat16* __restrict__ zl)
{
    int cid = blockIdx.x;
    int ch = cid & (NCH - 1);
    int bh = cid >> 4;
    int b = bh >> 4, h = bh & (HH - 1);
    int wid = threadIdx.x >> 5, lane = threadIdx.x & 31;

    __shared__ float s0[1024];
    __shared__ float sa[8][32];
    if (ch != 0) {
        for (int i = threadIdx.x; i < 1024; i += 256)
            s0[i] = S0[(size_t)cid * 1024 + i];
    }
    __syncthreads();

    float lw = lnw[h * HSZ + lane];
    float lb = lnb[h * HSZ + lane];

    size_t base = ((size_t)b * TT + (size_t)ch * CHL) * CC + h * HSZ + lane;
    for (int tt = 0; tt < 16; ++tt) {
        int t = wid * 16 + tt;
        size_t off = base + (size_t)t * CC;
        float yv = ylocal[off];
        if (ch != 0) {
            sa[wid][lane] = A[off];
            __syncwarp();
            float acc = 0.f;
            #pragma unroll
            for (int j4 = 0; j4 < 8; ++j4) {
                float4 a4 = *reinterpret_cast<const float4*>(&sa[wid][j4 * 4]);
                acc = fmaf(a4.x, s0[(j4*4+0)*32 + lane], acc);
                acc = fmaf(a4.y, s0[(j4*4+1)*32 + lane], acc);
                acc = fmaf(a4.z, s0[(j4*4+2)*32 + lane], acc);
                acc = fmaf(a4.w, s0[(j4*4+3)*32 + lane], acc);
            }
            yv += acc;
            __syncwarp();
        }
        float s = yv;
        #pragma unroll
        for (int o = 16; o; o >>= 1) s += __shfl_xor_sync(0xffffffffu, s, o);
        float mu = s * (1.f / 32.f);
        float dv = yv - mu;
        float q = dv * dv;
        #pragma unroll
        for (int o = 16; o; o >>= 1) q += __shfl_xor_sync(0xffffffffu, q, o);
        float yn = dv * rsqrtf(q * (1.f / 32.f) + 1e-5f);
        float z = (yn * lw + lb) * gate[off];
        wsplit(z, zh, zl, off);
    }
}

// ---------------------------------------------------------------------------
extern "C" void kernel_launch(void* const* d_in, const int* in_sizes, int n_in,
                              void* d_out, int out_size) {
    const float* x      = (const float*)d_in[0];
    const float* tmaa_x = (const float*)d_in[1];
    const float* tmaa_w = (const float*)d_in[2];
    const float* tmaa_k = (const float*)d_in[3];
    const float* tmaa_v = (const float*)d_in[4];
    const float* tmaa_r = (const float*)d_in[5];
    const float* tmaa_g = (const float*)d_in[6];
    const float* w1     = (const float*)d_in[7];   // (C,160)
    const float* w2     = (const float*)d_in[8];   // (5,32,C)
    const float* tdecay = (const float*)d_in[9];   // (C,)
    const float* tdw1   = (const float*)d_in[10];  // (C,64)
    const float* tdw2   = (const float*)d_in[11];  // (64,C)
    const float* faaaa  = (const float*)d_in[12];  // (H,HS)
    const float* Wr     = (const float*)d_in[13];
    const float* Wk     = (const float*)d_in[14];
    const float* Wv     = (const float*)d_in[15];
    const float* Wg     = (const float*)d_in[16];
    const float* Wo     = (const float*)d_in[17];
    const float* lnw    = (const float*)d_in[18];
    const float* lnb    = (const float*)d_in[19];
    float* out = (float*)d_out;

    unsigned char* S;
    cudaGetSymbolAddress((void**)&S, g_scratch);
    __nv_bfloat16* mixbh = (__nv_bfloat16*)(S + O_MIX);   // bf16 (BT,160)
    float* db   = (float*)(S + O_DB);
    float* rb   = (float*)(S + O_RB);
    float* kb   = (float*)(S + O_KB);
    float* vb   = (float*)(S + O_VB);
    float* gb   = (float*)(S + O_GB);
    float* yb   = (float*)(S + O_YB);
    float* ab   = (float*)(S + O_AB);
    float* lb   = (float*)(S + O_LB);
    float* pb   = (float*)(S + O_PB);
    float* s0b  = (float*)(S + O_S0);
    __nv_bfloat16* xwh = (__nv_bfloat16*)(S + O_XWH);
    __nv_bfloat16* xwl = (__nv_bfloat16*)(S + O_XWL);
    __nv_bfloat16* w64h = (__nv_bfloat16*)(S + O_W64H);
    __nv_bfloat16* w64l = (__nv_bfloat16*)(S + O_W64L);
    __nv_bfloat16* kh = (__nv_bfloat16*)(S + O_KH);
    __nv_bfloat16* kl = (__nv_bfloat16*)(S + O_KL);
    __nv_bfloat16* vh = (__nv_bfloat16*)(S + O_VH);
    __nv_bfloat16* vl = (__nv_bfloat16*)(S + O_VL);
    __nv_bfloat16* rh = (__nv_bfloat16*)(S + O_RH);
    __nv_bfloat16* rl = (__nv_bfloat16*)(S + O_RL);
    __nv_bfloat16* gh = (__nv_bfloat16*)(S + O_GH);
    __nv_bfloat16* gl = (__nv_bfloat16*)(S + O_GL);
    __nv_bfloat16* zh = (__nv_bfloat16*)(S + O_ZH);
    __nv_bfloat16* zl = (__nv_bfloat16*)(S + O_ZL);
    __nv_bfloat16* xxh = (__nv_bfloat16*)(S + O_XXH);
    __nv_bfloat16* xxl = (__nv_bfloat16*)(S + O_XXL);
    __nv_bfloat16* wrh = (__nv_bfloat16*)(S + O_WRH);
    __nv_bfloat16* wrl = (__nv_bfloat16*)(S + O_WRL);
    __nv_bfloat16* wkh = (__nv_bfloat16*)(S + O_WKH);
    __nv_bfloat16* wkl = (__nv_bfloat16*)(S + O_WKL);
    __nv_bfloat16* wvh = (__nv_bfloat16*)(S + O_WVH);
    __nv_bfloat16* wvl = (__nv_bfloat16*)(S + O_WVL);
    __nv_bfloat16* wgh = (__nv_bfloat16*)(S + O_WGH);
    __nv_bfloat16* wgl = (__nv_bfloat16*)(S + O_WGL);
    __nv_bfloat16* woh = (__nv_bfloat16*)(S + O_WOH);
    __nv_bfloat16* wol = (__nv_bfloat16*)(S + O_WOL);
    __nv_bfloat16* t1h = (__nv_bfloat16*)(S + O_T1H);
    __nv_bfloat16* t1l = (__nv_bfloat16*)(S + O_T1L);
    __nv_bfloat16* t2h = (__nv_bfloat16*)(S + O_T2H);
    __nv_bfloat16* t2l = (__nv_bfloat16*)(S + O_T2L);
    __nv_bfloat16* m1h = (__nv_bfloat16*)(S + O_M1H);
    __nv_bfloat16* m1l = (__nv_bfloat16*)(S + O_M1L);
    __nv_bfloat16* mixp = (__nv_bfloat16*)(S + O_MIXP);
    __nv_bfloat16* w2t  = (__nv_bfloat16*)(S + O_W2T);

    cudaFuncSetAttribute(tgemm_kernel<true, 0>, cudaFuncAttributeMaxDynamicSharedMemorySize, TG_SMEM);
    cudaFuncSetAttribute(tgemm_kernel<false, 0>, cudaFuncAttributeMaxDynamicSharedMemorySize, TG_SMEM);
    cudaFuncSetAttribute(tgemm2_kernel<16, 1, 1>, cudaFuncAttributeMaxDynamicSharedMemorySize, TG_SMEM);
    cudaFuncSetAttribute(tgemm2_kernel<2, 3, 0>, cudaFuncAttributeMaxDynamicSharedMemorySize, TG_SMEM);
    cudaFuncSetAttribute(tgemm2_kernel<16, 1, 2>, cudaFuncAttributeMaxDynamicSharedMemorySize, TG_SMEM);

    // 0) weight splits
    convw_all_kernel<<<dim3(1024, 5), 256>>>(Wr, Wk, Wv, Wg, Wo,
                                             wrh, wrl, wkh, wkl, wvh, wvl,
                                             wgh, wgl, woh, wol);
    convtd_kernel<<<dim3(320, 5), 256>>>(tdw1, tdw2, w1, w2,
                                         t1h, t1l, t2h, t2l, m1h, m1l, w2t);

    // 1) xxx = x + (shift(x)-x)*maa_x -> bf16 split
    prep_split_kernel<<<(int)(UEL / 256), 256>>>(x, tmaa_x, xxh, xxl);

    // 2) mix = tanh(xxx @ w1)  [BT,160] on tensor cores, bf16 out
    tgemm2_kernel<16, 1, 2><<<dim3(2, BT / 128), 256, TG_SMEM>>>(
        xxh, xxl, m1h, m1l, nullptr, mixbh, nullptr, nullptr, 160);

    // 3a) back-projection GEMMs: mixproj_f = mix_f @ W2T[f]  (batched over f)
    tgemm3_kernel<<<dim3(4, BT / 128, 5), 256>>>(mixbh, w2t, mixp);

    // 3b) elementwise 5-way token mixing -> bf16 hi/lo operands
    mixapply_kernel<<<(int)(UEL / 1024), 256>>>(x, mixp, tmaa_w, tmaa_k, tmaa_v,
                                                tmaa_r, tmaa_g, xwh, xwl, kh, kl,
                                                vh, vl, rh, rl, gh, gl);

    // 4) 4 projections in ONE batched tensor-core launch (z==3 (g) = silu)
    {
        TGBatch bt_{};
        bt_.ah[0] = rh; bt_.al[0] = rl; bt_.bh[0] = wrh; bt_.bl[0] = wrl; bt_.c[0] = rb;
        bt_.ah[1] = kh; bt_.al[1] = kl; bt_.bh[1] = wkh; bt_.bl[1] = wkl; bt_.c[1] = kb;
        bt_.ah[2] = vh; bt_.al[2] = vl; bt_.bh[2] = wvh; bt_.bl[2] = wvl; bt_.c[2] = vb;
        bt_.ah[3] = gh; bt_.al[3] = gl; bt_.bh[3] = wgh; bt_.bl[3] = wgl; bt_.c[3] = gb;
        tgemm_kernel<true, 0><<<dim3(4, BT / 128, 4), 256, TG_SMEM>>>(
            bt_, nullptr, nullptr, nullptr, nullptr, nullptr);
    }

    // 5) decay MLP on tensor cores
    tgemm2_kernel<16, 1, 1><<<dim3(1, BT / 128), 256, TG_SMEM>>>(
        xwh, xwl, t1h, t1l, nullptr, w64h, w64l, nullptr, 64);
    tgemm2_kernel<2, 3, 0><<<dim3(4, BT / 128), 256, TG_SMEM>>>(
        w64h, w64l, t2h, t2l, db, nullptr, nullptr, tdecay, 512);

    // 6) WKV6 chunked scan: local scans -> state scan -> correction + gn fused
    wkv_chunk_kernel<<<NCID / 8, 256>>>(rb, kb, vb, db, faaaa, yb, ab, lb, pb);
    wkv_state_scan_kernel<<<BQ * HH, 1024>>>(lb, pb, s0b);
    wkv_apply_gn_kernel<<<NCID, 256>>>(yb, ab, s0b, gb, lnw, lnb, zh, zl);

    // 7) out = z @ Wo^T (tensor cores)
    {
        TGBatch dummy{};
        tgemm_kernel<false, 0><<<dim3(4, BT / 128), 256, TG_SMEM>>>(
            dummy, zh, zl, woh, wol, out);
    }
}